// round 2
// baseline (speedup 1.0000x reference)
#include <cuda_runtime.h>
#include <math.h>

#define HW    12544   // 112*112
#define NTOK  12544   // 256 windows * 49 tokens
#define CDIM  512

// ---------------- scratch (device globals; no allocation allowed) ----------
__device__ float g_xw [NTOK * 512];    // LN1 + shift + window partition, token-major
__device__ float g_qkv[NTOK * 1536];   // qkv
__device__ float g_att[NTOK * 512];    // attention output (heads concat), token-major
__device__ float g_x1 [HW   * 512];    // x + attn (pixel-major [p, C])
__device__ float g_x2 [HW   * 512];    // LN2(x1)
__device__ float g_h  [NTOK * 2048];   // GELU(fc1)

// ---------------- helpers --------------------------------------------------
__device__ __forceinline__ int tok2pix(int t) {
    int win = t / 49, n = t % 49;
    int hs = (win >> 4) * 7 + n / 7;
    int ws = (win & 15) * 7 + n % 7;
    int ho = hs + 3; if (ho >= 112) ho -= 112;
    int wo = ws + 3; if (wo >= 112) wo -= 112;
    return ho * 112 + wo;
}

__device__ __forceinline__ float gelu_tanh(float x) {
    float x3 = x * x * x;
    return 0.5f * x * (1.0f + tanhf(0.7978845608028654f * (x + 0.044715f * x3)));
}

// block(256) reduction of (sum, sumsq); result broadcast to all threads
__device__ __forceinline__ void block_reduce2(float& s, float& q) {
    __shared__ float sh_s[8], sh_q[8];
    #pragma unroll
    for (int o = 16; o > 0; o >>= 1) {
        s += __shfl_down_sync(0xffffffffu, s, o);
        q += __shfl_down_sync(0xffffffffu, q, o);
    }
    int lane = threadIdx.x & 31, wid = threadIdx.x >> 5;
    if (lane == 0) { sh_s[wid] = s; sh_q[wid] = q; }
    __syncthreads();
    if (wid == 0) {
        s = (lane < 8) ? sh_s[lane] : 0.f;
        q = (lane < 8) ? sh_q[lane] : 0.f;
        #pragma unroll
        for (int o = 4; o > 0; o >>= 1) {
            s += __shfl_down_sync(0xffffffffu, s, o);
            q += __shfl_down_sync(0xffffffffu, q, o);
        }
        if (lane == 0) { sh_s[0] = s; sh_q[0] = q; }
    }
    __syncthreads();
    s = sh_s[0]; q = sh_q[0];
}

// ---------------- LN1 + cyclic shift + window partition --------------------
// one block per token; reads x [C,HW], writes g_xw [t, C]
__global__ __launch_bounds__(256) void ln1_kernel(
    const float* __restrict__ x, const float* __restrict__ w,
    const float* __restrict__ b, float* __restrict__ out)
{
    int t = blockIdx.x;
    int p = tok2pix(t);
    int c = threadIdx.x;
    float v1 = x[(size_t)c * HW + p];
    float v2 = x[(size_t)(c + 256) * HW + p];
    float s = v1 + v2, q = v1 * v1 + v2 * v2;
    block_reduce2(s, q);
    float mean = s * (1.0f / 512.0f);
    float var  = q * (1.0f / 512.0f) - mean * mean;
    float rstd = rsqrtf(var + 1e-5f);
    out[(size_t)t * 512 + c]       = (v1 - mean) * rstd * w[c]       + b[c];
    out[(size_t)t * 512 + c + 256] = (v2 - mean) * rstd * w[c + 256] + b[c + 256];
}

// ---------------- LN2 (pixel-major input/output) ----------------------------
__global__ __launch_bounds__(256) void ln2_kernel(
    const float* __restrict__ x, const float* __restrict__ w,
    const float* __restrict__ b, float* __restrict__ out)
{
    int p = blockIdx.x;
    int c = threadIdx.x;
    float v1 = x[(size_t)p * 512 + c];
    float v2 = x[(size_t)p * 512 + c + 256];
    float s = v1 + v2, q = v1 * v1 + v2 * v2;
    block_reduce2(s, q);
    float mean = s * (1.0f / 512.0f);
    float var  = q * (1.0f / 512.0f) - mean * mean;
    float rstd = rsqrtf(var + 1e-5f);
    out[(size_t)p * 512 + c]       = (v1 - mean) * rstd * w[c]       + b[c];
    out[(size_t)p * 512 + c + 256] = (v2 - mean) * rstd * w[c + 256] + b[c + 256];
}

// ---------------- windowed attention ----------------------------------------
// grid = 256 windows * 16 heads; block = 128 threads
__global__ __launch_bounds__(128) void attn_kernel(
    const float* __restrict__ qkv, const float* __restrict__ rpb,
    float* __restrict__ out)
{
    int w    = blockIdx.x >> 4;
    int head = blockIdx.x & 15;
    __shared__ float qs[49][33], ks[49][33], vs[49][33];
    __shared__ float S[49][49];
    int tid = threadIdx.x;

    for (int idx = tid; idx < 49 * 32; idx += 128) {
        int n = idx >> 5, d = idx & 31;
        const float* base = qkv + (size_t)(w * 49 + n) * 1536 + head * 32 + d;
        qs[n][d] = base[0];
        ks[n][d] = base[512];
        vs[n][d] = base[1024];
    }
    __syncthreads();

    int wh = w >> 4, ww = w & 15;
    for (int idx = tid; idx < 49 * 49; idx += 128) {
        int i = idx / 49, j = idx % 49;
        float s = 0.f;
        #pragma unroll
        for (int d = 0; d < 32; d++) s += qs[i][d] * ks[j][d];
        s *= 0.17677669529663687f;  // 1/sqrt(32)
        int ri = i / 7, ci = i % 7, rj = j / 7, cj = j % 7;
        s += rpb[((ri - rj + 6) * 13 + (ci - cj + 6)) * 16 + head];
        // shifted-window mask (region ids on shifted grid)
        int hi = wh * 7 + ri, wi = ww * 7 + ci;
        int hj = wh * 7 + rj, wj = ww * 7 + cj;
        int regi = ((hi < 105) ? 0 : (hi < 109 ? 1 : 2)) * 3 + ((wi < 105) ? 0 : (wi < 109 ? 1 : 2));
        int regj = ((hj < 105) ? 0 : (hj < 109 ? 1 : 2)) * 3 + ((wj < 105) ? 0 : (wj < 109 ? 1 : 2));
        if (regi != regj) s -= 1e9f;
        S[i][j] = s;
    }
    __syncthreads();

    if (tid < 49) {
        float mx = -1e30f;
        for (int j = 0; j < 49; j++) mx = fmaxf(mx, S[tid][j]);
        float sum = 0.f;
        for (int j = 0; j < 49; j++) { float e = expf(S[tid][j] - mx); S[tid][j] = e; sum += e; }
        float inv = 1.0f / sum;
        for (int j = 0; j < 49; j++) S[tid][j] *= inv;
    }
    __syncthreads();

    for (int idx = tid; idx < 49 * 32; idx += 128) {
        int i = idx >> 5, d = idx & 31;
        float o = 0.f;
        #pragma unroll
        for (int j = 0; j < 49; j++) o += S[i][j] * vs[j][d];
        out[(size_t)(w * 49 + i) * 512 + head * 32 + d] = o;
    }
}

// ---------------- SGEMM: C = A[M,K] @ B[N,K]^T (+bias, +epilogue) -----------
// 128x128 tile, BK=8, 256 threads, 8x8 per-thread register tile.
// mode 0: C[m*N+n] = acc + bias[n]                          (qkv)
// mode 1: C[m*N+n] = gelu(acc + bias[n])                    (fc1)
// mode 2: p=tok2pix(m); C[p*512+n] = acc+bias[n]+res[n*HW+p]  (proj + unshift + residual, res = x CHW)
// mode 3: C[n*HW+m]  = acc+bias[n]+res[m*512+n]             (fc2 + residual + CHW transpose, res = x1)
__global__ __launch_bounds__(256) void sgemm_nt(
    const float* __restrict__ A, const float* __restrict__ B,
    const float* __restrict__ bias, const float* __restrict__ res,
    float* __restrict__ C, int M, int N, int K, int mode)
{
    __shared__ float As[8][128];
    __shared__ float Bs[8][128];
    int tid = threadIdx.x;
    int m0 = blockIdx.y * 128;
    int n0 = blockIdx.x * 128;
    int tx = tid & 15, ty = tid >> 4;
    int lr = tid >> 1;
    int lk = (tid & 1) * 4;
    const float* Ap = A + (size_t)(m0 + lr) * K + lk;
    const float* Bp = B + (size_t)(n0 + lr) * K + lk;

    float acc[8][8];
    #pragma unroll
    for (int i = 0; i < 8; i++)
        #pragma unroll
        for (int j = 0; j < 8; j++) acc[i][j] = 0.f;

    for (int k0 = 0; k0 < K; k0 += 8) {
        float4 av = *(const float4*)(Ap + k0);
        float4 bv = *(const float4*)(Bp + k0);
        As[lk + 0][lr] = av.x; As[lk + 1][lr] = av.y; As[lk + 2][lr] = av.z; As[lk + 3][lr] = av.w;
        Bs[lk + 0][lr] = bv.x; Bs[lk + 1][lr] = bv.y; Bs[lk + 2][lr] = bv.z; Bs[lk + 3][lr] = bv.w;
        __syncthreads();
        #pragma unroll
        for (int k = 0; k < 8; k++) {
            float a[8], bb[8];
            #pragma unroll
            for (int i = 0; i < 8; i++) a[i]  = As[k][ty * 8 + i];
            #pragma unroll
            for (int j = 0; j < 8; j++) bb[j] = Bs[k][tx * 8 + j];
            #pragma unroll
            for (int i = 0; i < 8; i++)
                #pragma unroll
                for (int j = 0; j < 8; j++)
                    acc[i][j] += a[i] * bb[j];
        }
        __syncthreads();
    }

    if (mode <= 1) {
        #pragma unroll
        for (int i = 0; i < 8; i++) {
            int m = m0 + ty * 8 + i;
            float* cp = C + (size_t)m * N + n0 + tx * 8;
            #pragma unroll
            for (int j = 0; j < 8; j++) {
                float v = acc[i][j] + bias[n0 + tx * 8 + j];
                if (mode == 1) v = gelu_tanh(v);
                cp[j] = v;
            }
        }
    } else if (mode == 2) {
        #pragma unroll
        for (int i = 0; i < 8; i++) {
            int m = m0 + ty * 8 + i;
            int p = tok2pix(m);
            #pragma unroll
            for (int j = 0; j < 8; j++) {
                int n = n0 + tx * 8 + j;
                C[(size_t)p * 512 + n] = acc[i][j] + bias[n] + res[(size_t)n * HW + p];
            }
        }
    } else {  // mode 3
        #pragma unroll
        for (int i = 0; i < 8; i++) {
            int m = m0 + ty * 8 + i;
            #pragma unroll
            for (int j = 0; j < 8; j++) {
                int n = n0 + tx * 8 + j;
                C[(size_t)n * HW + m] = acc[i][j] + bias[n] + res[(size_t)m * 512 + n];
            }
        }
    }
}

// ---------------- launcher --------------------------------------------------
extern "C" void kernel_launch(void* const* d_in, const int* in_sizes, int n_in,
                              void* d_out, int out_size)
{
    const float* x     = (const float*)d_in[0];
    const float* n1w   = (const float*)d_in[1];
    const float* n1b   = (const float*)d_in[2];
    const float* qkvw  = (const float*)d_in[3];
    const float* qkvb  = (const float*)d_in[4];
    const float* projw = (const float*)d_in[5];
    const float* projb = (const float*)d_in[6];
    const float* rpb   = (const float*)d_in[7];
    const float* n2w   = (const float*)d_in[8];
    const float* n2b   = (const float*)d_in[9];
    const float* f1w   = (const float*)d_in[10];
    const float* f1b   = (const float*)d_in[11];
    const float* f2w   = (const float*)d_in[12];
    const float* f2b   = (const float*)d_in[13];
    float* out = (float*)d_out;

    float *xw, *qkv, *att, *x1, *x2, *h;
    cudaGetSymbolAddress((void**)&xw,  g_xw);
    cudaGetSymbolAddress((void**)&qkv, g_qkv);
    cudaGetSymbolAddress((void**)&att, g_att);
    cudaGetSymbolAddress((void**)&x1,  g_x1);
    cudaGetSymbolAddress((void**)&x2,  g_x2);
    cudaGetSymbolAddress((void**)&h,   g_h);

    // 1) LN1 + shift + window partition
    ln1_kernel<<<NTOK, 256>>>(x, n1w, n1b, xw);
    // 2) QKV GEMM  [12544,512] x [1536,512]^T
    sgemm_nt<<<dim3(1536 / 128, NTOK / 128), 256>>>(xw, qkvw, qkvb, nullptr, qkv, NTOK, 1536, 512, 0);
    // 3) windowed attention (bias + mask + softmax + @v)
    attn_kernel<<<256 * 16, 128>>>(qkv, rpb, att);
    // 4) proj GEMM + unshift/unpartition + residual(x) -> x1 [p,C]
    sgemm_nt<<<dim3(512 / 128, NTOK / 128), 256>>>(att, projw, projb, x, x1, NTOK, 512, 512, 2);
    // 5) LN2
    ln2_kernel<<<HW, 256>>>(x1, n2w, n2b, x2);
    // 6) FC1 + GELU
    sgemm_nt<<<dim3(2048 / 128, NTOK / 128), 256>>>(x2, f1w, f1b, nullptr, h, NTOK, 2048, 512, 1);
    // 7) FC2 + residual(x1) + transpose to [C,H,W] output
    sgemm_nt<<<dim3(512 / 128, NTOK / 128), 256>>>(h, f2w, f2b, x1, out, NTOK, 512, 2048, 3);
}

// round 6
// speedup vs baseline: 2.8502x; 2.8502x over previous
#include <cuda_runtime.h>
#include <cstdint>
#include <math.h>

#define HW    12544   // 112*112
#define NTOK  12544   // 256 windows * 49 tokens

// ---------------- scratch (device globals; no allocation allowed) ----------
__device__ float g_xw [NTOK * 512];    // LN1 + shift + window partition (tf32-rounded)
__device__ float g_qkv[NTOK * 1536];   // qkv (fp32)
__device__ float g_att[NTOK * 512];    // attention output (tf32-rounded)
__device__ float g_x1 [HW   * 512];    // x + attn (pixel-major, fp32)
__device__ float g_x2 [HW   * 512];    // LN2(x1) (tf32-rounded)
__device__ float g_h  [NTOK * 2048];   // GELU(fc1) (tf32-rounded)
// tf32-rounded weights
__device__ float g_wq[1536 * 512];
__device__ float g_wp[512 * 512];
__device__ float g_w1[2048 * 512];
__device__ float g_w2[512 * 2048];

// ---------------- helpers ----------------------------------------------------
__device__ __forceinline__ uint32_t smem_u32(const void* p) {
    uint32_t a;
    asm("{ .reg .u64 t; cvta.to.shared.u64 t, %1; cvt.u32.u64 %0, t; }" : "=r"(a) : "l"(p));
    return a;
}
__device__ __forceinline__ float to_tf32(float x) {
    float y;
    asm("cvt.rna.tf32.f32 %0, %1;" : "=f"(y) : "f"(x));
    return y;
}
__device__ __forceinline__ void cp16(uint32_t dst, const void* src) {
    asm volatile("cp.async.cg.shared.global [%0], [%1], 16;" :: "r"(dst), "l"(src));
}
__device__ __forceinline__ int tok2pix(int t) {
    int win = t / 49, n = t % 49;
    int hs = (win >> 4) * 7 + n / 7;
    int ws = (win & 15) * 7 + n % 7;
    int ho = hs + 3; if (ho >= 112) ho -= 112;
    int wo = ws + 3; if (wo >= 112) wo -= 112;
    return ho * 112 + wo;
}
__device__ __forceinline__ float gelu_tanh(float x) {
    float x3 = x * x * x;
    return 0.5f * x * (1.0f + tanhf(0.7978845608028654f * (x + 0.044715f * x3)));
}
__device__ __forceinline__ void block_reduce2(float& s, float& q) {
    __shared__ float sh_s[8], sh_q[8];
    #pragma unroll
    for (int o = 16; o > 0; o >>= 1) {
        s += __shfl_down_sync(0xffffffffu, s, o);
        q += __shfl_down_sync(0xffffffffu, q, o);
    }
    int lane = threadIdx.x & 31, wid = threadIdx.x >> 5;
    if (lane == 0) { sh_s[wid] = s; sh_q[wid] = q; }
    __syncthreads();
    if (wid == 0) {
        s = (lane < 8) ? sh_s[lane] : 0.f;
        q = (lane < 8) ? sh_q[lane] : 0.f;
        #pragma unroll
        for (int o = 4; o > 0; o >>= 1) {
            s += __shfl_down_sync(0xffffffffu, s, o);
            q += __shfl_down_sync(0xffffffffu, q, o);
        }
        if (lane == 0) { sh_s[0] = s; sh_q[0] = q; }
    }
    __syncthreads();
    s = sh_s[0]; q = sh_q[0];
}

// ---------------- weight tf32 rounding pre-pass ------------------------------
__global__ __launch_bounds__(256) void round_tf32_kernel(
    const float* __restrict__ src, float* __restrict__ dst, int n)
{
    int i = blockIdx.x * 256 + threadIdx.x;
    int stride = gridDim.x * 256;
    for (; i < n; i += stride) dst[i] = to_tf32(src[i]);
}

// ---------------- LN kernels (outputs tf32-rounded: GEMM inputs) -------------
__global__ __launch_bounds__(256) void ln1_kernel(
    const float* __restrict__ x, const float* __restrict__ w,
    const float* __restrict__ b, float* __restrict__ out)
{
    int t = blockIdx.x;
    int p = tok2pix(t);
    int c = threadIdx.x;
    float v1 = x[(size_t)c * HW + p];
    float v2 = x[(size_t)(c + 256) * HW + p];
    float s = v1 + v2, q = v1 * v1 + v2 * v2;
    block_reduce2(s, q);
    float mean = s * (1.0f / 512.0f);
    float var  = q * (1.0f / 512.0f) - mean * mean;
    float rstd = rsqrtf(var + 1e-5f);
    out[(size_t)t * 512 + c]       = to_tf32((v1 - mean) * rstd * w[c]       + b[c]);
    out[(size_t)t * 512 + c + 256] = to_tf32((v2 - mean) * rstd * w[c + 256] + b[c + 256]);
}

__global__ __launch_bounds__(256) void ln2_kernel(
    const float* __restrict__ x, const float* __restrict__ w,
    const float* __restrict__ b, float* __restrict__ out)
{
    int p = blockIdx.x;
    int c = threadIdx.x;
    float v1 = x[(size_t)p * 512 + c];
    float v2 = x[(size_t)p * 512 + c + 256];
    float s = v1 + v2, q = v1 * v1 + v2 * v2;
    block_reduce2(s, q);
    float mean = s * (1.0f / 512.0f);
    float var  = q * (1.0f / 512.0f) - mean * mean;
    float rstd = rsqrtf(var + 1e-5f);
    out[(size_t)p * 512 + c]       = to_tf32((v1 - mean) * rstd * w[c]       + b[c]);
    out[(size_t)p * 512 + c + 256] = to_tf32((v2 - mean) * rstd * w[c + 256] + b[c + 256]);
}

// ---------------- windowed attention (fp32; output tf32-rounded) -------------
__global__ __launch_bounds__(128) void attn_kernel(
    const float* __restrict__ qkv, const float* __restrict__ rpb,
    float* __restrict__ out)
{
    int w    = blockIdx.x >> 4;
    int head = blockIdx.x & 15;
    __shared__ float qs[49][33], ks[49][33], vs[49][33];
    __shared__ float S[49][49];
    int tid = threadIdx.x;

    for (int idx = tid; idx < 49 * 32; idx += 128) {
        int n = idx >> 5, d = idx & 31;
        const float* base = qkv + (size_t)(w * 49 + n) * 1536 + head * 32 + d;
        qs[n][d] = base[0];
        ks[n][d] = base[512];
        vs[n][d] = base[1024];
    }
    __syncthreads();

    int wh = w >> 4, ww = w & 15;
    for (int idx = tid; idx < 49 * 49; idx += 128) {
        int i = idx / 49, j = idx % 49;
        float s = 0.f;
        #pragma unroll
        for (int d = 0; d < 32; d++) s += qs[i][d] * ks[j][d];
        s *= 0.17677669529663687f;
        int ri = i / 7, ci = i % 7, rj = j / 7, cj = j % 7;
        s += rpb[((ri - rj + 6) * 13 + (ci - cj + 6)) * 16 + head];
        int hi = wh * 7 + ri, wi = ww * 7 + ci;
        int hj = wh * 7 + rj, wj = ww * 7 + cj;
        int regi = ((hi < 105) ? 0 : (hi < 109 ? 1 : 2)) * 3 + ((wi < 105) ? 0 : (wi < 109 ? 1 : 2));
        int regj = ((hj < 105) ? 0 : (hj < 109 ? 1 : 2)) * 3 + ((wj < 105) ? 0 : (wj < 109 ? 1 : 2));
        if (regi != regj) s -= 1e9f;
        S[i][j] = s;
    }
    __syncthreads();

    if (tid < 49) {
        float mx = -1e30f;
        for (int j = 0; j < 49; j++) mx = fmaxf(mx, S[tid][j]);
        float sum = 0.f;
        for (int j = 0; j < 49; j++) { float e = expf(S[tid][j] - mx); S[tid][j] = e; sum += e; }
        float inv = 1.0f / sum;
        for (int j = 0; j < 49; j++) S[tid][j] *= inv;
    }
    __syncthreads();

    for (int idx = tid; idx < 49 * 32; idx += 128) {
        int i = idx >> 5, d = idx & 31;
        float o = 0.f;
        #pragma unroll
        for (int j = 0; j < 49; j++) o += S[i][j] * vs[j][d];
        out[(size_t)(w * 49 + i) * 512 + head * 32 + d] = to_tf32(o);
    }
}

// ---------------- tf32 mma.sync GEMM ------------------------------------------
// C = A[M,K] @ B[N,K]^T. Tile 128x128, BK=32, 256 thr, 8 warps (2x4), warp 64x32.
// m16n8k8 tf32 HMMA, padded smem (stride 36 floats -> conflict-free frags),
// cp.async double buffering.
// mode 0: C = acc+bias                     (qkv)
// mode 1: C = tf32(gelu(acc+bias))         (fc1 -> g_h)
// mode 2: p=tok2pix(m); C[p*512+n]=acc+bias+res[n*HW+p]   (proj)
// mode 3: C[n*HW+m]=acc+bias+res[m*512+n]                 (fc2 -> out CHW)

#define BM 128
#define BN 128
#define BK 32
#define PAD 36
#define SM_FLOATS (4 * BM * PAD)   // A0,B0,A1,B1

__device__ __forceinline__ void mma8(float* c, const uint32_t* a, const uint32_t* b) {
    asm volatile(
        "mma.sync.aligned.m16n8k8.row.col.f32.tf32.tf32.f32 "
        "{%0,%1,%2,%3}, {%4,%5,%6,%7}, {%8,%9}, {%0,%1,%2,%3};"
        : "+f"(c[0]), "+f"(c[1]), "+f"(c[2]), "+f"(c[3])
        : "r"(a[0]), "r"(a[1]), "r"(a[2]), "r"(a[3]), "r"(b[0]), "r"(b[1]));
}

__device__ __forceinline__ void load_chunk(
    const float* __restrict__ A, const float* __restrict__ B, int K,
    int m0, int n0, int tid, uint32_t a_s, uint32_t b_s, int ch)
{
    int kb = ch * BK;
    #pragma unroll
    for (int t = 0; t < 4; t++) {
        int idx = tid + t * 256;          // 0..1023
        int r = idx >> 3, c16 = idx & 7;
        uint32_t so = (uint32_t)(r * PAD + c16 * 4) * 4;
        cp16(a_s + so, A + (size_t)(m0 + r) * K + kb + c16 * 4);
        cp16(b_s + so, B + (size_t)(n0 + r) * K + kb + c16 * 4);
    }
    asm volatile("cp.async.commit_group;" ::: "memory");
}

__global__ __launch_bounds__(256, 2) void gemm_mma(
    const float* __restrict__ A, const float* __restrict__ B,
    const float* __restrict__ bias, const float* __restrict__ res,
    float* __restrict__ C, int N, int K, int mode)
{
    extern __shared__ float sm[];
    uint32_t sb = smem_u32(sm);
    int tid = threadIdx.x;
    int wid = tid >> 5, lane = tid & 31;
    int g = lane >> 2, t4 = lane & 3;
    int wm = wid >> 2, wn = wid & 3;
    int m0 = blockIdx.y * BM, n0 = blockIdx.x * BN;

    float* As[2] = { sm,              sm + 2 * BM * PAD };
    float* Bs[2] = { sm + BM * PAD,   sm + 3 * BM * PAD };
    uint32_t Asu[2] = { sb,                      sb + 2 * BM * PAD * 4 };
    uint32_t Bsu[2] = { sb + BM * PAD * 4,       sb + 3 * BM * PAD * 4 };

    float c[4][4][4];
    #pragma unroll
    for (int i = 0; i < 4; i++)
        #pragma unroll
        for (int j = 0; j < 4; j++)
            #pragma unroll
            for (int r = 0; r < 4; r++) c[i][j][r] = 0.f;

    int nch = K / BK;
    load_chunk(A, B, K, m0, n0, tid, Asu[0], Bsu[0], 0);
    load_chunk(A, B, K, m0, n0, tid, Asu[1], Bsu[1], 1);

    for (int ch = 0; ch < nch; ch++) {
        if (ch + 1 < nch) asm volatile("cp.async.wait_group 1;" ::: "memory");
        else              asm volatile("cp.async.wait_group 0;" ::: "memory");
        __syncthreads();

        const float* as = As[ch & 1];
        const float* bs = Bs[ch & 1];
        #pragma unroll
        for (int ks = 0; ks < 4; ks++) {
            int kk = ks * 8;
            uint32_t af[4][4], bf[4][2];
            #pragma unroll
            for (int mt = 0; mt < 4; mt++) {
                const float* ap = as + (wm * 64 + mt * 16) * PAD + kk;
                af[mt][0] = __float_as_uint(ap[g * PAD + t4]);
                af[mt][1] = __float_as_uint(ap[(g + 8) * PAD + t4]);
                af[mt][2] = __float_as_uint(ap[g * PAD + t4 + 4]);
                af[mt][3] = __float_as_uint(ap[(g + 8) * PAD + t4 + 4]);
            }
            #pragma unroll
            for (int nt = 0; nt < 4; nt++) {
                const float* bp = bs + (wn * 32 + nt * 8 + g) * PAD + kk;
                bf[nt][0] = __float_as_uint(bp[t4]);
                bf[nt][1] = __float_as_uint(bp[t4 + 4]);
            }
            #pragma unroll
            for (int mt = 0; mt < 4; mt++)
                #pragma unroll
                for (int nt = 0; nt < 4; nt++)
                    mma8(c[mt][nt], af[mt], bf[nt]);
        }
        __syncthreads();
        if (ch + 2 < nch)
            load_chunk(A, B, K, m0, n0, tid, Asu[ch & 1], Bsu[ch & 1], ch + 2);
    }

    // ---------------- epilogue ----------------
    if (mode <= 1) {
        #pragma unroll
        for (int mt = 0; mt < 4; mt++)
            #pragma unroll
            for (int hf = 0; hf < 2; hf++) {
                int m = m0 + wm * 64 + mt * 16 + g + hf * 8;
                #pragma unroll
                for (int nt = 0; nt < 4; nt++) {
                    int n = n0 + wn * 32 + nt * 8 + t4 * 2;
                    float v0 = c[mt][nt][hf * 2 + 0] + bias[n];
                    float v1 = c[mt][nt][hf * 2 + 1] + bias[n + 1];
                    if (mode == 1) {
                        v0 = to_tf32(gelu_tanh(v0));
                        v1 = to_tf32(gelu_tanh(v1));
                    }
                    float2 v = make_float2(v0, v1);
                    *(float2*)(C + (size_t)m * N + n) = v;
                }
            }
    } else if (mode == 2) {
        #pragma unroll
        for (int mt = 0; mt < 4; mt++)
            #pragma unroll
            for (int hf = 0; hf < 2; hf++) {
                int m = m0 + wm * 64 + mt * 16 + g + hf * 8;
                int p = tok2pix(m);
                #pragma unroll
                for (int nt = 0; nt < 4; nt++) {
                    int n = n0 + wn * 32 + nt * 8 + t4 * 2;
                    float v0 = c[mt][nt][hf * 2 + 0] + bias[n]     + res[(size_t)n * HW + p];
                    float v1 = c[mt][nt][hf * 2 + 1] + bias[n + 1] + res[(size_t)(n + 1) * HW + p];
                    float2 v = make_float2(v0, v1);
                    *(float2*)(C + (size_t)p * 512 + n) = v;
                }
            }
    } else {  // mode 3: out[n*HW+m] = acc + bias[n] + res[m*512+n]
        #pragma unroll
        for (int mt = 0; mt < 4; mt++)
            #pragma unroll
            for (int hf = 0; hf < 2; hf++) {
                int m = m0 + wm * 64 + mt * 16 + g + hf * 8;
                #pragma unroll
                for (int nt = 0; nt < 4; nt++) {
                    int n = n0 + wn * 32 + nt * 8 + t4 * 2;
                    float r0 = res[(size_t)m * 512 + n];
                    float r1 = res[(size_t)m * 512 + n + 1];
                    C[(size_t)n * HW + m]       = c[mt][nt][hf * 2 + 0] + bias[n]     + r0;
                    C[(size_t)(n + 1) * HW + m] = c[mt][nt][hf * 2 + 1] + bias[n + 1] + r1;
                }
            }
    }
}

// ---------------- launcher --------------------------------------------------
extern "C" void kernel_launch(void* const* d_in, const int* in_sizes, int n_in,
                              void* d_out, int out_size)
{
    const float* x     = (const float*)d_in[0];
    const float* n1w   = (const float*)d_in[1];
    const float* n1b   = (const float*)d_in[2];
    const float* qkvw  = (const float*)d_in[3];
    const float* qkvb  = (const float*)d_in[4];
    const float* projw = (const float*)d_in[5];
    const float* projb = (const float*)d_in[6];
    const float* rpb   = (const float*)d_in[7];
    const float* n2w   = (const float*)d_in[8];
    const float* n2b   = (const float*)d_in[9];
    const float* f1w   = (const float*)d_in[10];
    const float* f1b   = (const float*)d_in[11];
    const float* f2w   = (const float*)d_in[12];
    const float* f2b   = (const float*)d_in[13];
    float* out = (float*)d_out;

    float *xw, *qkv, *att, *x1, *x2, *h, *wq, *wp, *w1, *w2;
    cudaGetSymbolAddress((void**)&xw,  g_xw);
    cudaGetSymbolAddress((void**)&qkv, g_qkv);
    cudaGetSymbolAddress((void**)&att, g_att);
    cudaGetSymbolAddress((void**)&x1,  g_x1);
    cudaGetSymbolAddress((void**)&x2,  g_x2);
    cudaGetSymbolAddress((void**)&h,   g_h);
    cudaGetSymbolAddress((void**)&wq,  g_wq);
    cudaGetSymbolAddress((void**)&wp,  g_wp);
    cudaGetSymbolAddress((void**)&w1,  g_w1);
    cudaGetSymbolAddress((void**)&w2,  g_w2);

    cudaFuncSetAttribute(gemm_mma, cudaFuncAttributeMaxDynamicSharedMemorySize,
                         SM_FLOATS * 4);

    // 0) round weights to tf32 (rna) once per launch
    round_tf32_kernel<<<512, 256>>>(qkvw,  wq, 1536 * 512);
    round_tf32_kernel<<<512, 256>>>(projw, wp, 512 * 512);
    round_tf32_kernel<<<512, 256>>>(f1w,   w1, 2048 * 512);
    round_tf32_kernel<<<512, 256>>>(f2w,   w2, 512 * 2048);

    // 1) LN1 + shift + window partition (tf32 out)
    ln1_kernel<<<NTOK, 256>>>(x, n1w, n1b, xw);
    // 2) QKV GEMM [12544,512] x [1536,512]^T
    gemm_mma<<<dim3(1536 / 128, NTOK / 128), 256, SM_FLOATS * 4>>>(xw, wq, qkvb, nullptr, qkv, 1536, 512, 0);
    // 3) windowed attention
    attn_kernel<<<256 * 16, 128>>>(qkv, rpb, att);
    // 4) proj GEMM + unshift/unpartition + residual(x) -> x1 [p,C]
    gemm_mma<<<dim3(512 / 128, NTOK / 128), 256, SM_FLOATS * 4>>>(att, wp, projb, x, x1, 512, 512, 2);
    // 5) LN2 (tf32 out)
    ln2_kernel<<<HW, 256>>>(x1, n2w, n2b, x2);
    // 6) FC1 + GELU (tf32 out)
    gemm_mma<<<dim3(2048 / 128, NTOK / 128), 256, SM_FLOATS * 4>>>(x2, w1, f1b, nullptr, h, 2048, 512, 1);
    // 7) FC2 + residual(x1) + transpose to [C,H,W] output
    gemm_mma<<<dim3(512 / 128, NTOK / 128), 256, SM_FLOATS * 4>>>(h, w2, f2b, x1, out, 512, 2048, 3);
}

// round 9
// speedup vs baseline: 4.5618x; 1.6005x over previous
#include <cuda_runtime.h>
#include <cuda_fp16.h>
#include <cstdint>
#include <math.h>

#define HW    12544   // 112*112
#define NTOK  12544   // 256 windows * 49 tokens

// ---------------- scratch (device globals; no allocation allowed) ----------
// __align__(256) is load-bearing: cp.async.cg 16B needs 16B-aligned global srcs.
__device__ __align__(256) __half g_xw [NTOK * 512];    // LN1 + shift + window partition (fp16)
__device__ __align__(256) float  g_qkv[NTOK * 1536];   // qkv (fp32)
__device__ __align__(256) __half g_att[NTOK * 512];    // attention output (fp16)
__device__ __align__(256) float  g_x1 [HW   * 512];    // x + attn (pixel-major, fp32)
__device__ __align__(256) __half g_x2 [HW   * 512];    // LN2(x1) (fp16)
__device__ __align__(256) __half g_h  [NTOK * 2048];   // GELU(fc1) (fp16)
// fp16 weights
__device__ __align__(256) __half g_wq[1536 * 512];
__device__ __align__(256) __half g_wp[512 * 512];
__device__ __align__(256) __half g_w1[2048 * 512];
__device__ __align__(256) __half g_w2[512 * 2048];

// ---------------- helpers ----------------------------------------------------
__device__ __forceinline__ uint32_t smem_u32(const void* p) {
    uint32_t a;
    asm("{ .reg .u64 t; cvta.to.shared.u64 t, %1; cvt.u32.u64 %0, t; }" : "=r"(a) : "l"(p));
    return a;
}
__device__ __forceinline__ void cp16(uint32_t dst, const void* src) {
    asm volatile("cp.async.cg.shared.global [%0], [%1], 16;" :: "r"(dst), "l"(src));
}
__device__ __forceinline__ int tok2pix(int t) {
    int win = t / 49, n = t % 49;
    int hs = (win >> 4) * 7 + n / 7;
    int ws = (win & 15) * 7 + n % 7;
    int ho = hs + 3; if (ho >= 112) ho -= 112;
    int wo = ws + 3; if (wo >= 112) wo -= 112;
    return ho * 112 + wo;
}
__device__ __forceinline__ float gelu_tanh(float x) {
    float x3 = x * x * x;
    return 0.5f * x * (1.0f + tanhf(0.7978845608028654f * (x + 0.044715f * x3)));
}
__device__ __forceinline__ void block_reduce2(float& s, float& q) {
    __shared__ float sh_s[8], sh_q[8];
    #pragma unroll
    for (int o = 16; o > 0; o >>= 1) {
        s += __shfl_down_sync(0xffffffffu, s, o);
        q += __shfl_down_sync(0xffffffffu, q, o);
    }
    int lane = threadIdx.x & 31, wid = threadIdx.x >> 5;
    if (lane == 0) { sh_s[wid] = s; sh_q[wid] = q; }
    __syncthreads();
    if (wid == 0) {
        s = (lane < 8) ? sh_s[lane] : 0.f;
        q = (lane < 8) ? sh_q[lane] : 0.f;
        #pragma unroll
        for (int o = 4; o > 0; o >>= 1) {
            s += __shfl_down_sync(0xffffffffu, s, o);
            q += __shfl_down_sync(0xffffffffu, q, o);
        }
        if (lane == 0) { sh_s[0] = s; sh_q[0] = q; }
    }
    __syncthreads();
    s = sh_s[0]; q = sh_q[0];
}

// ---------------- weight fp32 -> fp16 pre-pass -------------------------------
__global__ __launch_bounds__(256) void f2h_kernel(
    const float* __restrict__ src, __half* __restrict__ dst, int n)
{
    int i = blockIdx.x * 256 + threadIdx.x;
    int stride = gridDim.x * 256;
    for (; i < n; i += stride) dst[i] = __float2half_rn(src[i]);
}

// ---------------- LN kernels (fp16 outputs: GEMM inputs) ---------------------
__global__ __launch_bounds__(256) void ln1_kernel(
    const float* __restrict__ x, const float* __restrict__ w,
    const float* __restrict__ b, __half* __restrict__ out)
{
    int t = blockIdx.x;
    int p = tok2pix(t);
    int c = threadIdx.x;
    float v1 = x[(size_t)c * HW + p];
    float v2 = x[(size_t)(c + 256) * HW + p];
    float s = v1 + v2, q = v1 * v1 + v2 * v2;
    block_reduce2(s, q);
    float mean = s * (1.0f / 512.0f);
    float var  = q * (1.0f / 512.0f) - mean * mean;
    float rstd = rsqrtf(var + 1e-5f);
    out[(size_t)t * 512 + c]       = __float2half_rn((v1 - mean) * rstd * w[c]       + b[c]);
    out[(size_t)t * 512 + c + 256] = __float2half_rn((v2 - mean) * rstd * w[c + 256] + b[c + 256]);
}

__global__ __launch_bounds__(256) void ln2_kernel(
    const float* __restrict__ x, const float* __restrict__ w,
    const float* __restrict__ b, __half* __restrict__ out)
{
    int p = blockIdx.x;
    int c = threadIdx.x;
    float v1 = x[(size_t)p * 512 + c];
    float v2 = x[(size_t)p * 512 + c + 256];
    float s = v1 + v2, q = v1 * v1 + v2 * v2;
    block_reduce2(s, q);
    float mean = s * (1.0f / 512.0f);
    float var  = q * (1.0f / 512.0f) - mean * mean;
    float rstd = rsqrtf(var + 1e-5f);
    out[(size_t)p * 512 + c]       = __float2half_rn((v1 - mean) * rstd * w[c]       + b[c]);
    out[(size_t)p * 512 + c + 256] = __float2half_rn((v2 - mean) * rstd * w[c + 256] + b[c + 256]);
}

// ---------------- windowed attention (fp32 math; fp16 output) ----------------
__global__ __launch_bounds__(128) void attn_kernel(
    const float* __restrict__ qkv, const float* __restrict__ rpb,
    __half* __restrict__ out)
{
    int w    = blockIdx.x >> 4;
    int head = blockIdx.x & 15;
    __shared__ float qs[49][33], ks[49][33];
    // __align__(16) is load-bearing: float4 LDS from vs requires a 16B-aligned
    // base; static __shared__ float arrays are only 4B-aligned by default.
    __shared__ __align__(16) float vs[49][36];
    __shared__ float S[49][49];
    int tid = threadIdx.x;

    for (int idx = tid; idx < 49 * 32; idx += 128) {
        int n = idx >> 5, d = idx & 31;
        const float* base = qkv + (size_t)(w * 49 + n) * 1536 + head * 32 + d;
        qs[n][d] = base[0];
        ks[n][d] = base[512];
        vs[n][d] = base[1024];
    }
    __syncthreads();

    int wh = w >> 4, ww = w & 15;
    // QK^T with q-row cached in registers (items: 49 rows x 7 j-blocks)
    for (int idx = tid; idx < 49 * 7; idx += 128) {
        int i  = idx / 7;
        int jb = (idx % 7) * 7;
        float qr[32];
        #pragma unroll
        for (int d = 0; d < 32; d++) qr[d] = qs[i][d];
        int ri = i / 7, ci = i % 7;
        int hi = wh * 7 + ri, wi = ww * 7 + ci;
        int regi = ((hi < 105) ? 0 : (hi < 109 ? 1 : 2)) * 3 + ((wi < 105) ? 0 : (wi < 109 ? 1 : 2));
        #pragma unroll
        for (int jo = 0; jo < 7; jo++) {
            int j = jb + jo;
            float s = 0.f;
            #pragma unroll
            for (int d = 0; d < 32; d++) s += qr[d] * ks[j][d];
            s *= 0.17677669529663687f;
            int rj = j / 7, cj = j % 7;
            s += rpb[((ri - rj + 6) * 13 + (ci - cj + 6)) * 16 + head];
            int hj = wh * 7 + rj, wj = ww * 7 + cj;
            int regj = ((hj < 105) ? 0 : (hj < 109 ? 1 : 2)) * 3 + ((wj < 105) ? 0 : (wj < 109 ? 1 : 2));
            if (regi != regj) s -= 1e9f;
            S[i][j] = s;
        }
    }
    __syncthreads();

    if (tid < 49) {
        float mx = -1e30f;
        for (int j = 0; j < 49; j++) mx = fmaxf(mx, S[tid][j]);
        float sum = 0.f;
        for (int j = 0; j < 49; j++) { float e = expf(S[tid][j] - mx); S[tid][j] = e; sum += e; }
        float inv = 1.0f / sum;
        for (int j = 0; j < 49; j++) S[tid][j] *= inv;
    }
    __syncthreads();

    // S @ V with float4 V loads (items: 49 rows x 8 d-quads)
    for (int idx = tid; idx < 49 * 8; idx += 128) {
        int i  = idx >> 3;
        int dq = (idx & 7) * 4;
        float4 acc = make_float4(0.f, 0.f, 0.f, 0.f);
        #pragma unroll 7
        for (int j = 0; j < 49; j++) {
            float sv = S[i][j];
            float4 v = *(const float4*)&vs[j][dq];
            acc.x += sv * v.x; acc.y += sv * v.y;
            acc.z += sv * v.z; acc.w += sv * v.w;
        }
        __half* op = out + (size_t)(w * 49 + i) * 512 + head * 32 + dq;
        *(__half2*)(op)     = __floats2half2_rn(acc.x, acc.y);
        *(__half2*)(op + 2) = __floats2half2_rn(acc.z, acc.w);
    }
}

// ---------------- fp16 mma.sync GEMM ------------------------------------------
// C = A[M,K] @ B[N,K]^T, fp16 operands, fp32 accum.
// Tile 128x128, BK=64 halves, 256 thr, 8 warps (2x4), warp 64x32,
// m16n8k16 HMMA, padded smem (stride 72 halves = 144B -> conflict-free),
// cp.async double buffering.

#define BM 128
#define BN 128
#define BKH 64
#define PADH 72
#define BUF_HALFS (BM * PADH)                    // 9216 halves = 18432 B
#define SM_BYTES (4 * BUF_HALFS * 2)             // 73728 B

__device__ __forceinline__ void mma16(float* c, const uint32_t* a, const uint32_t* b) {
    asm volatile(
        "mma.sync.aligned.m16n8k16.row.col.f32.f16.f16.f32 "
        "{%0,%1,%2,%3}, {%4,%5,%6,%7}, {%8,%9}, {%0,%1,%2,%3};"
        : "+f"(c[0]), "+f"(c[1]), "+f"(c[2]), "+f"(c[3])
        : "r"(a[0]), "r"(a[1]), "r"(a[2]), "r"(a[3]), "r"(b[0]), "r"(b[1]));
}

__device__ __forceinline__ void load_chunk(
    const __half* __restrict__ A, const __half* __restrict__ B, int K,
    int m0, int n0, int tid, uint32_t a_s, uint32_t b_s, int ch)
{
    int kb = ch * BKH;
    #pragma unroll
    for (int t = 0; t < 8; t++) {
        int idx = tid + t * 256;          // 0..2047
        int li  = idx & 1023;
        int r = li >> 3, c8 = li & 7;
        uint32_t so = (uint32_t)(r * 144 + c8 * 16);
        if (idx < 1024)
            cp16(a_s + so, A + (size_t)(m0 + r) * K + kb + c8 * 8);
        else
            cp16(b_s + so, B + (size_t)(n0 + r) * K + kb + c8 * 8);
    }
    asm volatile("cp.async.commit_group;" ::: "memory");
}

__global__ __launch_bounds__(256, 2) void gemm_mma(
    const __half* __restrict__ A, const __half* __restrict__ B,
    const float* __restrict__ bias, const float* __restrict__ res,
    void* __restrict__ Cv, int N, int K, int mode)
{
    extern __shared__ __half sm[];
    uint32_t sb = smem_u32(sm);
    int tid = threadIdx.x;
    int wid = tid >> 5, lane = tid & 31;
    int g = lane >> 2, t4 = lane & 3;
    int wm = wid >> 2, wn = wid & 3;
    int m0 = blockIdx.y * BM, n0 = blockIdx.x * BN;

    __half* As[2] = { sm,                sm + 2 * BUF_HALFS };
    __half* Bs[2] = { sm + BUF_HALFS,    sm + 3 * BUF_HALFS };
    uint32_t Asu[2] = { sb,                       sb + 2 * BUF_HALFS * 2 };
    uint32_t Bsu[2] = { sb + BUF_HALFS * 2,       sb + 3 * BUF_HALFS * 2 };

    float c[4][4][4];
    #pragma unroll
    for (int i = 0; i < 4; i++)
        #pragma unroll
        for (int j = 0; j < 4; j++)
            #pragma unroll
            for (int r = 0; r < 4; r++) c[i][j][r] = 0.f;

    int nch = K / BKH;
    load_chunk(A, B, K, m0, n0, tid, Asu[0], Bsu[0], 0);
    load_chunk(A, B, K, m0, n0, tid, Asu[1], Bsu[1], 1);

    for (int ch = 0; ch < nch; ch++) {
        if (ch + 1 < nch) asm volatile("cp.async.wait_group 1;" ::: "memory");
        else              asm volatile("cp.async.wait_group 0;" ::: "memory");
        __syncthreads();

        const __half* as = As[ch & 1];
        const __half* bs = Bs[ch & 1];
        #pragma unroll
        for (int ks = 0; ks < 4; ks++) {
            int kk = ks * 16;
            uint32_t af[4][4], bf[4][2];
            #pragma unroll
            for (int mt = 0; mt < 4; mt++) {
                const __half* ap = as + (wm * 64 + mt * 16) * PADH + kk;
                af[mt][0] = *(const uint32_t*)(ap + (size_t)g * PADH + t4 * 2);
                af[mt][1] = *(const uint32_t*)(ap + (size_t)(g + 8) * PADH + t4 * 2);
                af[mt][2] = *(const uint32_t*)(ap + (size_t)g * PADH + t4 * 2 + 8);
                af[mt][3] = *(const uint32_t*)(ap + (size_t)(g + 8) * PADH + t4 * 2 + 8);
            }
            #pragma unroll
            for (int nt = 0; nt < 4; nt++) {
                const __half* bp = bs + (wn * 32 + nt * 8 + g) * PADH + kk;
                bf[nt][0] = *(const uint32_t*)(bp + t4 * 2);
                bf[nt][1] = *(const uint32_t*)(bp + t4 * 2 + 8);
            }
            #pragma unroll
            for (int mt = 0; mt < 4; mt++)
                #pragma unroll
                for (int nt = 0; nt < 4; nt++)
                    mma16(c[mt][nt], af[mt], bf[nt]);
        }
        __syncthreads();
        if (ch + 2 < nch)
            load_chunk(A, B, K, m0, n0, tid, Asu[ch & 1], Bsu[ch & 1], ch + 2);
    }

    // ---------------- epilogue ----------------
    if (mode == 0) {
        float* C = (float*)Cv;
        #pragma unroll
        for (int mt = 0; mt < 4; mt++)
            #pragma unroll
            for (int hf = 0; hf < 2; hf++) {
                int m = m0 + wm * 64 + mt * 16 + g + hf * 8;
                #pragma unroll
                for (int nt = 0; nt < 4; nt++) {
                    int n = n0 + wn * 32 + nt * 8 + t4 * 2;
                    float2 v = make_float2(c[mt][nt][hf * 2 + 0] + bias[n],
                                           c[mt][nt][hf * 2 + 1] + bias[n + 1]);
                    *(float2*)(C + (size_t)m * N + n) = v;
                }
            }
    } else if (mode == 1) {
        __half* C = (__half*)Cv;
        #pragma unroll
        for (int mt = 0; mt < 4; mt++)
            #pragma unroll
            for (int hf = 0; hf < 2; hf++) {
                int m = m0 + wm * 64 + mt * 16 + g + hf * 8;
                #pragma unroll
                for (int nt = 0; nt < 4; nt++) {
                    int n = n0 + wn * 32 + nt * 8 + t4 * 2;
                    float v0 = gelu_tanh(c[mt][nt][hf * 2 + 0] + bias[n]);
                    float v1 = gelu_tanh(c[mt][nt][hf * 2 + 1] + bias[n + 1]);
                    *(__half2*)(C + (size_t)m * N + n) = __floats2half2_rn(v0, v1);
                }
            }
    } else if (mode == 2) {
        float* C = (float*)Cv;
        #pragma unroll
        for (int mt = 0; mt < 4; mt++)
            #pragma unroll
            for (int hf = 0; hf < 2; hf++) {
                int m = m0 + wm * 64 + mt * 16 + g + hf * 8;
                int p = tok2pix(m);
                #pragma unroll
                for (int nt = 0; nt < 4; nt++) {
                    int n = n0 + wn * 32 + nt * 8 + t4 * 2;
                    float2 v = make_float2(
                        c[mt][nt][hf * 2 + 0] + bias[n]     + res[(size_t)n * HW + p],
                        c[mt][nt][hf * 2 + 1] + bias[n + 1] + res[(size_t)(n + 1) * HW + p]);
                    *(float2*)(C + (size_t)p * 512 + n) = v;
                }
            }
    } else {  // mode 3
        float* C = (float*)Cv;
        #pragma unroll
        for (int mt = 0; mt < 4; mt++)
            #pragma unroll
            for (int hf = 0; hf < 2; hf++) {
                int m = m0 + wm * 64 + mt * 16 + g + hf * 8;
                #pragma unroll
                for (int nt = 0; nt < 4; nt++) {
                    int n = n0 + wn * 32 + nt * 8 + t4 * 2;
                    float r0 = res[(size_t)m * 512 + n];
                    float r1 = res[(size_t)m * 512 + n + 1];
                    C[(size_t)n * HW + m]       = c[mt][nt][hf * 2 + 0] + bias[n]     + r0;
                    C[(size_t)(n + 1) * HW + m] = c[mt][nt][hf * 2 + 1] + bias[n + 1] + r1;
                }
            }
    }
}

// ---------------- launcher --------------------------------------------------
extern "C" void kernel_launch(void* const* d_in, const int* in_sizes, int n_in,
                              void* d_out, int out_size)
{
    const float* x     = (const float*)d_in[0];
    const float* n1w   = (const float*)d_in[1];
    const float* n1b   = (const float*)d_in[2];
    const float* qkvw  = (const float*)d_in[3];
    const float* qkvb  = (const float*)d_in[4];
    const float* projw = (const float*)d_in[5];
    const float* projb = (const float*)d_in[6];
    const float* rpb   = (const float*)d_in[7];
    const float* n2w   = (const float*)d_in[8];
    const float* n2b   = (const float*)d_in[9];
    const float* f1w   = (const float*)d_in[10];
    const float* f1b   = (const float*)d_in[11];
    const float* f2w   = (const float*)d_in[12];
    const float* f2b   = (const float*)d_in[13];
    float* out = (float*)d_out;

    __half *xw, *att, *x2, *h, *wq, *wp, *w1, *w2;
    float *qkv, *x1;
    cudaGetSymbolAddress((void**)&xw,  g_xw);
    cudaGetSymbolAddress((void**)&qkv, g_qkv);
    cudaGetSymbolAddress((void**)&att, g_att);
    cudaGetSymbolAddress((void**)&x1,  g_x1);
    cudaGetSymbolAddress((void**)&x2,  g_x2);
    cudaGetSymbolAddress((void**)&h,   g_h);
    cudaGetSymbolAddress((void**)&wq,  g_wq);
    cudaGetSymbolAddress((void**)&wp,  g_wp);
    cudaGetSymbolAddress((void**)&w1,  g_w1);
    cudaGetSymbolAddress((void**)&w2,  g_w2);

    cudaFuncSetAttribute(gemm_mma, cudaFuncAttributeMaxDynamicSharedMemorySize, SM_BYTES);

    // 0) weights fp32 -> fp16 (once per launch)
    f2h_kernel<<<512, 256>>>(qkvw,  wq, 1536 * 512);
    f2h_kernel<<<512, 256>>>(projw, wp, 512 * 512);
    f2h_kernel<<<512, 256>>>(f1w,   w1, 2048 * 512);
    f2h_kernel<<<512, 256>>>(f2w,   w2, 512 * 2048);

    // 1) LN1 + shift + window partition (fp16 out)
    ln1_kernel<<<NTOK, 256>>>(x, n1w, n1b, xw);
    // 2) QKV GEMM [12544,512] x [1536,512]^T -> fp32
    gemm_mma<<<dim3(1536 / 128, NTOK / 128), 256, SM_BYTES>>>(xw, wq, qkvb, nullptr, qkv, 1536, 512, 0);
    // 3) windowed attention -> fp16
    attn_kernel<<<256 * 16, 128>>>(qkv, rpb, att);
    // 4) proj GEMM + unshift/unpartition + residual(x) -> x1 [p,C] fp32
    gemm_mma<<<dim3(512 / 128, NTOK / 128), 256, SM_BYTES>>>(att, wp, projb, x, x1, 512, 512, 2);
    // 5) LN2 (fp16 out)
    ln2_kernel<<<HW, 256>>>(x1, n2w, n2b, x2);
    // 6) FC1 + GELU (fp16 out)
    gemm_mma<<<dim3(2048 / 128, NTOK / 128), 256, SM_BYTES>>>(x2, w1, f1b, nullptr, h, 2048, 512, 1);
    // 7) FC2 + residual(x1) + transpose to [C,H,W] output
    gemm_mma<<<dim3(512 / 128, NTOK / 128), 256, SM_BYTES>>>(h, w2, f2b, x1, out, 512, 2048, 3);
}

// round 10
// speedup vs baseline: 4.9409x; 1.0831x over previous
#include <cuda_runtime.h>
#include <cuda_fp16.h>
#include <cstdint>
#include <math.h>

#define HW    12544   // 112*112
#define NTOK  12544   // 256 windows * 49 tokens

// ---------------- scratch (device globals; no allocation allowed) ----------
// __align__(256) is load-bearing: cp.async.cg 16B needs 16B-aligned global srcs.
__device__ __align__(256) __half g_xw [NTOK * 512];    // LN1 + shift + window partition (fp16)
__device__ __align__(256) __half g_qkv[NTOK * 1536];   // qkv (fp16)
__device__ __align__(256) __half g_att[NTOK * 512];    // attention output (fp16)
__device__ __align__(256) float  g_x1 [HW   * 512];    // x + attn (pixel-major, fp32)
__device__ __align__(256) __half g_x2 [HW   * 512];    // LN2(x1) (fp16)
__device__ __align__(256) __half g_h  [NTOK * 2048];   // GELU(fc1) (fp16)
// fp16 weights
__device__ __align__(256) __half g_wq[1536 * 512];
__device__ __align__(256) __half g_wp[512 * 512];
__device__ __align__(256) __half g_w1[2048 * 512];
__device__ __align__(256) __half g_w2[512 * 2048];

// ---------------- helpers ----------------------------------------------------
__device__ __forceinline__ uint32_t smem_u32(const void* p) {
    uint32_t a;
    asm("{ .reg .u64 t; cvta.to.shared.u64 t, %1; cvt.u32.u64 %0, t; }" : "=r"(a) : "l"(p));
    return a;
}
__device__ __forceinline__ void cp16(uint32_t dst, const void* src) {
    asm volatile("cp.async.cg.shared.global [%0], [%1], 16;" :: "r"(dst), "l"(src));
}
__device__ __forceinline__ void ldmx4(uint32_t* r, uint32_t addr) {
    asm volatile("ldmatrix.sync.aligned.m8n8.x4.shared.b16 {%0,%1,%2,%3}, [%4];"
                 : "=r"(r[0]), "=r"(r[1]), "=r"(r[2]), "=r"(r[3]) : "r"(addr));
}
__device__ __forceinline__ int tok2pix(int t) {
    int win = t / 49, n = t % 49;
    int hs = (win >> 4) * 7 + n / 7;
    int ws = (win & 15) * 7 + n % 7;
    int ho = hs + 3; if (ho >= 112) ho -= 112;
    int wo = ws + 3; if (wo >= 112) wo -= 112;
    return ho * 112 + wo;
}
__device__ __forceinline__ float gelu_tanh(float x) {
    float x3 = x * x * x;
    return 0.5f * x * (1.0f + tanhf(0.7978845608028654f * (x + 0.044715f * x3)));
}
__device__ __forceinline__ void block_reduce2(float& s, float& q) {
    __shared__ float sh_s[8], sh_q[8];
    #pragma unroll
    for (int o = 16; o > 0; o >>= 1) {
        s += __shfl_down_sync(0xffffffffu, s, o);
        q += __shfl_down_sync(0xffffffffu, q, o);
    }
    int lane = threadIdx.x & 31, wid = threadIdx.x >> 5;
    if (lane == 0) { sh_s[wid] = s; sh_q[wid] = q; }
    __syncthreads();
    if (wid == 0) {
        s = (lane < 8) ? sh_s[lane] : 0.f;
        q = (lane < 8) ? sh_q[lane] : 0.f;
        #pragma unroll
        for (int o = 4; o > 0; o >>= 1) {
            s += __shfl_down_sync(0xffffffffu, s, o);
            q += __shfl_down_sync(0xffffffffu, q, o);
        }
        if (lane == 0) { sh_s[0] = s; sh_q[0] = q; }
    }
    __syncthreads();
    s = sh_s[0]; q = sh_q[0];
}

// ---------------- fused weight fp32 -> fp16 pre-pass (one launch) ------------
// quarters (in float4 units): wq 196608 | wp 65536 | w1 262144 | w2 262144
__global__ __launch_bounds__(256) void f2h_all(
    const float* __restrict__ s0, const float* __restrict__ s1,
    const float* __restrict__ s2, const float* __restrict__ s3,
    __half* __restrict__ d0, __half* __restrict__ d1,
    __half* __restrict__ d2, __half* __restrict__ d3)
{
    int i = blockIdx.x * 256 + threadIdx.x;
    int stride = gridDim.x * 256;
    for (; i < 786432; i += stride) {
        int j = i; const float* s; __half* d;
        if      (j < 196608) { s = s0; d = d0; }
        else if (j < 262144) { s = s1; d = d1; j -= 196608; }
        else if (j < 524288) { s = s2; d = d2; j -= 262144; }
        else                 { s = s3; d = d3; j -= 524288; }
        float4 v = ((const float4*)s)[j];
        ((__half2*)d)[j * 2]     = __floats2half2_rn(v.x, v.y);
        ((__half2*)d)[j * 2 + 1] = __floats2half2_rn(v.z, v.w);
    }
}

// ---------------- LN kernels (fp16 outputs: GEMM inputs) ---------------------
__global__ __launch_bounds__(256) void ln1_kernel(
    const float* __restrict__ x, const float* __restrict__ w,
    const float* __restrict__ b, __half* __restrict__ out)
{
    int t = blockIdx.x;
    int p = tok2pix(t);
    int c = threadIdx.x;
    float v1 = x[(size_t)c * HW + p];
    float v2 = x[(size_t)(c + 256) * HW + p];
    float s = v1 + v2, q = v1 * v1 + v2 * v2;
    block_reduce2(s, q);
    float mean = s * (1.0f / 512.0f);
    float var  = q * (1.0f / 512.0f) - mean * mean;
    float rstd = rsqrtf(var + 1e-5f);
    out[(size_t)t * 512 + c]       = __float2half_rn((v1 - mean) * rstd * w[c]       + b[c]);
    out[(size_t)t * 512 + c + 256] = __float2half_rn((v2 - mean) * rstd * w[c + 256] + b[c + 256]);
}

__global__ __launch_bounds__(256) void ln2_kernel(
    const float* __restrict__ x, const float* __restrict__ w,
    const float* __restrict__ b, __half* __restrict__ out)
{
    int p = blockIdx.x;
    int c = threadIdx.x;
    float v1 = x[(size_t)p * 512 + c];
    float v2 = x[(size_t)p * 512 + c + 256];
    float s = v1 + v2, q = v1 * v1 + v2 * v2;
    block_reduce2(s, q);
    float mean = s * (1.0f / 512.0f);
    float var  = q * (1.0f / 512.0f) - mean * mean;
    float rstd = rsqrtf(var + 1e-5f);
    out[(size_t)p * 512 + c]       = __float2half_rn((v1 - mean) * rstd * w[c]       + b[c]);
    out[(size_t)p * 512 + c + 256] = __float2half_rn((v2 - mean) * rstd * w[c + 256] + b[c + 256]);
}

// ---------------- windowed attention (fp16 in, fp32 math, fp16 out) ----------
__global__ __launch_bounds__(128) void attn_kernel(
    const __half* __restrict__ qkv, const float* __restrict__ rpb,
    __half* __restrict__ out)
{
    int w    = blockIdx.x >> 4;
    int head = blockIdx.x & 15;
    __shared__ float qs[49][33], ks[49][33];
    // __align__(16): float4 LDS from vs requires a 16B-aligned base.
    __shared__ __align__(16) float vs[49][36];
    __shared__ float S[49][49];
    int tid = threadIdx.x;

    // load q/k/v as half2 pairs (coalesced-ish 4B accesses)
    for (int idx = tid; idx < 49 * 16; idx += 128) {
        int n = idx >> 4, dp = (idx & 15) * 2;
        const __half* base = qkv + (size_t)(w * 49 + n) * 1536 + head * 32 + dp;
        float2 q2 = __half22float2(*(const __half2*)(base));
        float2 k2 = __half22float2(*(const __half2*)(base + 512));
        float2 v2 = __half22float2(*(const __half2*)(base + 1024));
        qs[n][dp] = q2.x; qs[n][dp + 1] = q2.y;
        ks[n][dp] = k2.x; ks[n][dp + 1] = k2.y;
        vs[n][dp] = v2.x; vs[n][dp + 1] = v2.y;
    }
    __syncthreads();

    int wh = w >> 4, ww = w & 15;
    // QK^T with q-row cached in registers (items: 49 rows x 7 j-blocks)
    for (int idx = tid; idx < 49 * 7; idx += 128) {
        int i  = idx / 7;
        int jb = (idx % 7) * 7;
        float qr[32];
        #pragma unroll
        for (int d = 0; d < 32; d++) qr[d] = qs[i][d];
        int ri = i / 7, ci = i % 7;
        int hi = wh * 7 + ri, wi = ww * 7 + ci;
        int regi = ((hi < 105) ? 0 : (hi < 109 ? 1 : 2)) * 3 + ((wi < 105) ? 0 : (wi < 109 ? 1 : 2));
        #pragma unroll
        for (int jo = 0; jo < 7; jo++) {
            int j = jb + jo;
            float s = 0.f;
            #pragma unroll
            for (int d = 0; d < 32; d++) s += qr[d] * ks[j][d];
            s *= 0.17677669529663687f;
            int rj = j / 7, cj = j % 7;
            s += rpb[((ri - rj + 6) * 13 + (ci - cj + 6)) * 16 + head];
            int hj = wh * 7 + rj, wj = ww * 7 + cj;
            int regj = ((hj < 105) ? 0 : (hj < 109 ? 1 : 2)) * 3 + ((wj < 105) ? 0 : (wj < 109 ? 1 : 2));
            if (regi != regj) s -= 1e9f;
            S[i][j] = s;
        }
    }
    __syncthreads();

    if (tid < 49) {
        float mx = -1e30f;
        for (int j = 0; j < 49; j++) mx = fmaxf(mx, S[tid][j]);
        float sum = 0.f;
        for (int j = 0; j < 49; j++) { float e = expf(S[tid][j] - mx); S[tid][j] = e; sum += e; }
        float inv = 1.0f / sum;
        for (int j = 0; j < 49; j++) S[tid][j] *= inv;
    }
    __syncthreads();

    // S @ V with float4 V loads (items: 49 rows x 8 d-quads)
    for (int idx = tid; idx < 49 * 8; idx += 128) {
        int i  = idx >> 3;
        int dq = (idx & 7) * 4;
        float4 acc = make_float4(0.f, 0.f, 0.f, 0.f);
        #pragma unroll 7
        for (int j = 0; j < 49; j++) {
            float sv = S[i][j];
            float4 v = *(const float4*)&vs[j][dq];
            acc.x += sv * v.x; acc.y += sv * v.y;
            acc.z += sv * v.z; acc.w += sv * v.w;
        }
        __half* op = out + (size_t)(w * 49 + i) * 512 + head * 32 + dq;
        *(__half2*)(op)     = __floats2half2_rn(acc.x, acc.y);
        *(__half2*)(op + 2) = __floats2half2_rn(acc.z, acc.w);
    }
}

// ---------------- fp16 mma.sync GEMM with ldmatrix ---------------------------
// C = A[M,K] @ B[N,K]^T, fp16 operands, fp32 accum.
// Tile 128x128, BK=64 halves, 256 thr, 8 warps (2x4), warp 64x32,
// m16n8k16 HMMA, ldmatrix.x4 fragment loads, padded smem (144B row stride),
// cp.async double buffering.
// mode 0: C(f16) = acc+bias                     (qkv)
// mode 1: C(f16) = gelu(acc+bias)               (fc1)
// mode 2: p=tok2pix(m); C[p*512+n]=acc+bias+res[n*HW+p]   (proj, f32)
// mode 3: C[n*HW+m]=acc+bias+res[m*512+n]                 (fc2 -> out CHW, f32)

#define BM 128
#define BN 128
#define BKH 64
#define PADH 72
#define ROWB 144                                 // PADH * 2 bytes
#define BUF_HALFS (BM * PADH)                    // 9216 halves = 18432 B
#define SM_BYTES (4 * BUF_HALFS * 2)             // 73728 B

__device__ __forceinline__ void mma16(float* c, const uint32_t* a, uint32_t b0, uint32_t b1) {
    asm volatile(
        "mma.sync.aligned.m16n8k16.row.col.f32.f16.f16.f32 "
        "{%0,%1,%2,%3}, {%4,%5,%6,%7}, {%8,%9}, {%0,%1,%2,%3};"
        : "+f"(c[0]), "+f"(c[1]), "+f"(c[2]), "+f"(c[3])
        : "r"(a[0]), "r"(a[1]), "r"(a[2]), "r"(a[3]), "r"(b0), "r"(b1));
}

__device__ __forceinline__ void load_chunk(
    const __half* __restrict__ A, const __half* __restrict__ B, int K,
    int m0, int n0, int tid, uint32_t a_s, uint32_t b_s, int ch)
{
    int kb = ch * BKH;
    #pragma unroll
    for (int t = 0; t < 8; t++) {
        int idx = tid + t * 256;          // 0..2047
        int li  = idx & 1023;
        int r = li >> 3, c8 = li & 7;
        uint32_t so = (uint32_t)(r * ROWB + c8 * 16);
        if (idx < 1024)
            cp16(a_s + so, A + (size_t)(m0 + r) * K + kb + c8 * 8);
        else
            cp16(b_s + so, B + (size_t)(n0 + r) * K + kb + c8 * 8);
    }
    asm volatile("cp.async.commit_group;" ::: "memory");
}

__global__ __launch_bounds__(256, 2) void gemm_mma(
    const __half* __restrict__ A, const __half* __restrict__ B,
    const float* __restrict__ bias, const float* __restrict__ res,
    void* __restrict__ Cv, int N, int K, int mode)
{
    extern __shared__ __half sm[];
    uint32_t sb = smem_u32(sm);
    int tid = threadIdx.x;
    int wid = tid >> 5, lane = tid & 31;
    int g = lane >> 2, t4 = lane & 3;
    int wm = wid >> 2, wn = wid & 3;
    int m0 = blockIdx.y * BM, n0 = blockIdx.x * BN;

    uint32_t Asu[2] = { sb,                       sb + 2 * BUF_HALFS * 2 };
    uint32_t Bsu[2] = { sb + BUF_HALFS * 2,       sb + 3 * BUF_HALFS * 2 };

    // per-lane ldmatrix address offsets (within a buffer)
    // A: lanes 0-15 -> rows (lane&15) at k, lanes 16-31 -> same rows at k+8
    uint32_t a_off = (uint32_t)(wm * 64 + (lane & 15)) * ROWB + ((lane >> 4) ? 16u : 0u);
    // B: lane l -> row wn*32 + l  (4 groups of 8 rows = nt 0..3)
    uint32_t b_off = (uint32_t)(wn * 32 + lane) * ROWB;

    float c[4][4][4];
    #pragma unroll
    for (int i = 0; i < 4; i++)
        #pragma unroll
        for (int j = 0; j < 4; j++)
            #pragma unroll
            for (int r = 0; r < 4; r++) c[i][j][r] = 0.f;

    int nch = K / BKH;
    load_chunk(A, B, K, m0, n0, tid, Asu[0], Bsu[0], 0);
    load_chunk(A, B, K, m0, n0, tid, Asu[1], Bsu[1], 1);

    for (int ch = 0; ch < nch; ch++) {
        if (ch + 1 < nch) asm volatile("cp.async.wait_group 1;" ::: "memory");
        else              asm volatile("cp.async.wait_group 0;" ::: "memory");
        __syncthreads();

        uint32_t a_base = Asu[ch & 1] + a_off;
        uint32_t b_base = Bsu[ch & 1] + b_off;
        #pragma unroll
        for (int ks = 0; ks < 4; ks++) {
            uint32_t kbyte = ks * 32;                 // 16 halves
            uint32_t af[4][4], bq0[4], bq1[4];
            #pragma unroll
            for (int mt = 0; mt < 4; mt++)
                ldmx4(af[mt], a_base + mt * (16 * ROWB) + kbyte);
            ldmx4(bq0, b_base + kbyte);               // b0 for nt 0..3
            ldmx4(bq1, b_base + kbyte + 16);          // b1 for nt 0..3
            #pragma unroll
            for (int mt = 0; mt < 4; mt++)
                #pragma unroll
                for (int nt = 0; nt < 4; nt++)
                    mma16(c[mt][nt], af[mt], bq0[nt], bq1[nt]);
        }
        __syncthreads();
        if (ch + 2 < nch)
            load_chunk(A, B, K, m0, n0, tid, Asu[ch & 1], Bsu[ch & 1], ch + 2);
    }

    // ---------------- epilogue ----------------
    if (mode == 0) {
        __half* C = (__half*)Cv;
        #pragma unroll
        for (int mt = 0; mt < 4; mt++)
            #pragma unroll
            for (int hf = 0; hf < 2; hf++) {
                int m = m0 + wm * 64 + mt * 16 + g + hf * 8;
                #pragma unroll
                for (int nt = 0; nt < 4; nt++) {
                    int n = n0 + wn * 32 + nt * 8 + t4 * 2;
                    float v0 = c[mt][nt][hf * 2 + 0] + bias[n];
                    float v1 = c[mt][nt][hf * 2 + 1] + bias[n + 1];
                    *(__half2*)(C + (size_t)m * N + n) = __floats2half2_rn(v0, v1);
                }
            }
    } else if (mode == 1) {
        __half* C = (__half*)Cv;
        #pragma unroll
        for (int mt = 0; mt < 4; mt++)
            #pragma unroll
            for (int hf = 0; hf < 2; hf++) {
                int m = m0 + wm * 64 + mt * 16 + g + hf * 8;
                #pragma unroll
                for (int nt = 0; nt < 4; nt++) {
                    int n = n0 + wn * 32 + nt * 8 + t4 * 2;
                    float v0 = gelu_tanh(c[mt][nt][hf * 2 + 0] + bias[n]);
                    float v1 = gelu_tanh(c[mt][nt][hf * 2 + 1] + bias[n + 1]);
                    *(__half2*)(C + (size_t)m * N + n) = __floats2half2_rn(v0, v1);
                }
            }
    } else if (mode == 2) {
        float* C = (float*)Cv;
        #pragma unroll
        for (int mt = 0; mt < 4; mt++)
            #pragma unroll
            for (int hf = 0; hf < 2; hf++) {
                int m = m0 + wm * 64 + mt * 16 + g + hf * 8;
                int p = tok2pix(m);
                #pragma unroll
                for (int nt = 0; nt < 4; nt++) {
                    int n = n0 + wn * 32 + nt * 8 + t4 * 2;
                    float2 v = make_float2(
                        c[mt][nt][hf * 2 + 0] + bias[n]     + res[(size_t)n * HW + p],
                        c[mt][nt][hf * 2 + 1] + bias[n + 1] + res[(size_t)(n + 1) * HW + p]);
                    *(float2*)(C + (size_t)p * 512 + n) = v;
                }
            }
    } else {  // mode 3
        float* C = (float*)Cv;
        #pragma unroll
        for (int mt = 0; mt < 4; mt++)
            #pragma unroll
            for (int hf = 0; hf < 2; hf++) {
                int m = m0 + wm * 64 + mt * 16 + g + hf * 8;
                #pragma unroll
                for (int nt = 0; nt < 4; nt++) {
                    int n = n0 + wn * 32 + nt * 8 + t4 * 2;
                    float r0 = res[(size_t)m * 512 + n];
                    float r1 = res[(size_t)m * 512 + n + 1];
                    C[(size_t)n * HW + m]       = c[mt][nt][hf * 2 + 0] + bias[n]     + r0;
                    C[(size_t)(n + 1) * HW + m] = c[mt][nt][hf * 2 + 1] + bias[n + 1] + r1;
                }
            }
    }
}

// ---------------- launcher --------------------------------------------------
extern "C" void kernel_launch(void* const* d_in, const int* in_sizes, int n_in,
                              void* d_out, int out_size)
{
    const float* x     = (const float*)d_in[0];
    const float* n1w   = (const float*)d_in[1];
    const float* n1b   = (const float*)d_in[2];
    const float* qkvw  = (const float*)d_in[3];
    const float* qkvb  = (const float*)d_in[4];
    const float* projw = (const float*)d_in[5];
    const float* projb = (const float*)d_in[6];
    const float* rpb   = (const float*)d_in[7];
    const float* n2w   = (const float*)d_in[8];
    const float* n2b   = (const float*)d_in[9];
    const float* f1w   = (const float*)d_in[10];
    const float* f1b   = (const float*)d_in[11];
    const float* f2w   = (const float*)d_in[12];
    const float* f2b   = (const float*)d_in[13];
    float* out = (float*)d_out;

    __half *xw, *qkv, *att, *x2, *h, *wq, *wp, *w1, *w2;
    float *x1;
    cudaGetSymbolAddress((void**)&xw,  g_xw);
    cudaGetSymbolAddress((void**)&qkv, g_qkv);
    cudaGetSymbolAddress((void**)&att, g_att);
    cudaGetSymbolAddress((void**)&x1,  g_x1);
    cudaGetSymbolAddress((void**)&x2,  g_x2);
    cudaGetSymbolAddress((void**)&h,   g_h);
    cudaGetSymbolAddress((void**)&wq,  g_wq);
    cudaGetSymbolAddress((void**)&wp,  g_wp);
    cudaGetSymbolAddress((void**)&w1,  g_w1);
    cudaGetSymbolAddress((void**)&w2,  g_w2);

    cudaFuncSetAttribute(gemm_mma, cudaFuncAttributeMaxDynamicSharedMemorySize, SM_BYTES);

    // 0) all weights fp32 -> fp16 in one launch
    f2h_all<<<512, 256>>>(qkvw, projw, f1w, f2w, wq, wp, w1, w2);

    // 1) LN1 + shift + window partition (fp16 out)
    ln1_kernel<<<NTOK, 256>>>(x, n1w, n1b, xw);
    // 2) QKV GEMM [12544,512] x [1536,512]^T -> fp16
    gemm_mma<<<dim3(1536 / 128, NTOK / 128), 256, SM_BYTES>>>(xw, wq, qkvb, nullptr, qkv, 1536, 512, 0);
    // 3) windowed attention -> fp16
    attn_kernel<<<256 * 16, 128>>>(qkv, rpb, att);
    // 4) proj GEMM + unshift/unpartition + residual(x) -> x1 [p,C] fp32
    gemm_mma<<<dim3(512 / 128, NTOK / 128), 256, SM_BYTES>>>(att, wp, projb, x, x1, 512, 512, 2);
    // 5) LN2 (fp16 out)
    ln2_kernel<<<HW, 256>>>(x1, n2w, n2b, x2);
    // 6) FC1 + GELU (fp16 out)
    gemm_mma<<<dim3(2048 / 128, NTOK / 128), 256, SM_BYTES>>>(x2, w1, f1b, nullptr, h, 2048, 512, 1);
    // 7) FC2 + residual(x1) + transpose to [C,H,W] output
    gemm_mma<<<dim3(512 / 128, NTOK / 128), 256, SM_BYTES>>>(h, w2, f2b, x1, out, 512, 2048, 3);
}

// round 11
// speedup vs baseline: 5.1944x; 1.0513x over previous
#include <cuda_runtime.h>
#include <cuda_fp16.h>
#include <cstdint>
#include <math.h>

#define HW    12544   // 112*112
#define NTOK  12544   // 256 windows * 49 tokens

// ---------------- scratch (device globals; no allocation allowed) ----------
// __align__(256) is load-bearing: cp.async.cg 16B needs 16B-aligned global srcs.
__device__ __align__(256) __half g_xw [NTOK * 512];    // LN1 + shift + window partition (fp16)
__device__ __align__(256) __half g_qkv[NTOK * 1536];   // qkv (fp16)
__device__ __align__(256) __half g_att[NTOK * 512];    // attention output (fp16)
__device__ __align__(256) float  g_x1 [HW   * 512];    // x + attn (pixel-major, fp32)
__device__ __align__(256) __half g_x2 [HW   * 512];    // LN2(x1) (fp16)
__device__ __align__(256) __half g_h  [NTOK * 2048];   // GELU(fc1) (fp16)
// fp16 weights
__device__ __align__(256) __half g_wq[1536 * 512];
__device__ __align__(256) __half g_wp[512 * 512];
__device__ __align__(256) __half g_w1[2048 * 512];
__device__ __align__(256) __half g_w2[512 * 2048];

// ---------------- helpers ----------------------------------------------------
__device__ __forceinline__ uint32_t smem_u32(const void* p) {
    uint32_t a;
    asm("{ .reg .u64 t; cvta.to.shared.u64 t, %1; cvt.u32.u64 %0, t; }" : "=r"(a) : "l"(p));
    return a;
}
__device__ __forceinline__ void cp16(uint32_t dst, const void* src) {
    asm volatile("cp.async.cg.shared.global [%0], [%1], 16;" :: "r"(dst), "l"(src));
}
__device__ __forceinline__ void ldmx4(uint32_t* r, uint32_t addr) {
    asm volatile("ldmatrix.sync.aligned.m8n8.x4.shared.b16 {%0,%1,%2,%3}, [%4];"
                 : "=r"(r[0]), "=r"(r[1]), "=r"(r[2]), "=r"(r[3]) : "r"(addr));
}
__device__ __forceinline__ int tok2pix(int t) {
    int win = t / 49, n = t % 49;
    int hs = (win >> 4) * 7 + n / 7;
    int ws = (win & 15) * 7 + n % 7;
    int ho = hs + 3; if (ho >= 112) ho -= 112;
    int wo = ws + 3; if (wo >= 112) wo -= 112;
    return ho * 112 + wo;
}
__device__ __forceinline__ int pix2tok(int p) {
    int ho = p / 112, wo = p % 112;
    int hs = ho - 3; if (hs < 0) hs += 112;
    int ws = wo - 3; if (ws < 0) ws += 112;
    return ((hs / 7) * 16 + ws / 7) * 49 + (hs % 7) * 7 + ws % 7;
}
__device__ __forceinline__ float gelu_tanh(float x) {
    float x3 = x * x * x;
    return 0.5f * x * (1.0f + tanhf(0.7978845608028654f * (x + 0.044715f * x3)));
}
__device__ __forceinline__ void block_reduce2(float& s, float& q) {
    __shared__ float sh_s[8], sh_q[8];
    #pragma unroll
    for (int o = 16; o > 0; o >>= 1) {
        s += __shfl_down_sync(0xffffffffu, s, o);
        q += __shfl_down_sync(0xffffffffu, q, o);
    }
    int lane = threadIdx.x & 31, wid = threadIdx.x >> 5;
    if (lane == 0) { sh_s[wid] = s; sh_q[wid] = q; }
    __syncthreads();
    if (wid == 0) {
        s = (lane < 8) ? sh_s[lane] : 0.f;
        q = (lane < 8) ? sh_q[lane] : 0.f;
        #pragma unroll
        for (int o = 4; o > 0; o >>= 1) {
            s += __shfl_down_sync(0xffffffffu, s, o);
            q += __shfl_down_sync(0xffffffffu, q, o);
        }
        if (lane == 0) { sh_s[0] = s; sh_q[0] = q; }
    }
    __syncthreads();
    s = sh_s[0]; q = sh_q[0];
}

// ---------------- fused weight fp32 -> fp16 pre-pass (one launch) ------------
__global__ __launch_bounds__(256) void f2h_all(
    const float* __restrict__ s0, const float* __restrict__ s1,
    const float* __restrict__ s2, const float* __restrict__ s3,
    __half* __restrict__ d0, __half* __restrict__ d1,
    __half* __restrict__ d2, __half* __restrict__ d3)
{
    int i = blockIdx.x * 256 + threadIdx.x;
    int stride = gridDim.x * 256;
    for (; i < 786432; i += stride) {
        int j = i; const float* s; __half* d;
        if      (j < 196608) { s = s0; d = d0; }
        else if (j < 262144) { s = s1; d = d1; j -= 196608; }
        else if (j < 524288) { s = s2; d = d2; j -= 262144; }
        else                 { s = s3; d = d3; j -= 524288; }
        float4 v = ((const float4*)s)[j];
        ((__half2*)d)[j * 2]     = __floats2half2_rn(v.x, v.y);
        ((__half2*)d)[j * 2 + 1] = __floats2half2_rn(v.z, v.w);
    }
}

// ---------------- LN1: coalesced, 32 pixels per block ------------------------
// block = 256 thr = (px 0..31) x (cg 0..7); each cg covers 64 contiguous channels.
// All global loads are warp-coalesced over px. Output staged in smem then
// written as coalesced half2 rows to token-major layout (shift+partition fused).
__global__ __launch_bounds__(256) void ln1_kernel(
    const float* __restrict__ x, const float* __restrict__ w,
    const float* __restrict__ b, __half* __restrict__ out)
{
    __shared__ float ssum[8][33], ssq[8][33];
    __shared__ float smean[32], srstd[32];
    __shared__ __half sbuf[32][514];   // row stride 514 halves -> conflict-free
    int tid = threadIdx.x, px = tid & 31, cg = tid >> 5;
    int p = blockIdx.x * 32 + px;

    float s = 0.f, q = 0.f;
    #pragma unroll 8
    for (int ci = 0; ci < 64; ci++) {
        float v = x[(size_t)(cg * 64 + ci) * HW + p];
        s += v; q += v * v;
    }
    ssum[cg][px] = s; ssq[cg][px] = q;
    __syncthreads();
    if (tid < 32) {
        float S_ = 0.f, Q_ = 0.f;
        #pragma unroll
        for (int g2 = 0; g2 < 8; g2++) { S_ += ssum[g2][tid]; Q_ += ssq[g2][tid]; }
        float mean = S_ * (1.0f / 512.0f);
        float var  = Q_ * (1.0f / 512.0f) - mean * mean;
        smean[tid] = mean; srstd[tid] = rsqrtf(var + 1e-5f);
    }
    __syncthreads();
    float mean = smean[px], rstd = srstd[px];
    #pragma unroll 8
    for (int ci = 0; ci < 64; ci++) {
        int c = cg * 64 + ci;
        float v = x[(size_t)c * HW + p];
        sbuf[px][c] = __float2half_rn((v - mean) * rstd * __ldg(w + c) + __ldg(b + c));
    }
    __syncthreads();
    int p0 = blockIdx.x * 32;
    for (int r = 0; r < 32; r++) {
        int t = pix2tok(p0 + r);
        *(__half2*)(out + (size_t)t * 512 + tid * 2) = *(__half2*)&sbuf[r][tid * 2];
    }
}

// ---------------- LN2 (pixel-major; already coalesced) -----------------------
__global__ __launch_bounds__(256) void ln2_kernel(
    const float* __restrict__ x, const float* __restrict__ w,
    const float* __restrict__ b, __half* __restrict__ out)
{
    int p = blockIdx.x;
    int c = threadIdx.x;
    float v1 = x[(size_t)p * 512 + c];
    float v2 = x[(size_t)p * 512 + c + 256];
    float s = v1 + v2, q = v1 * v1 + v2 * v2;
    block_reduce2(s, q);
    float mean = s * (1.0f / 512.0f);
    float var  = q * (1.0f / 512.0f) - mean * mean;
    float rstd = rsqrtf(var + 1e-5f);
    out[(size_t)p * 512 + c]       = __float2half_rn((v1 - mean) * rstd * w[c]       + b[c]);
    out[(size_t)p * 512 + c + 256] = __float2half_rn((v2 - mean) * rstd * w[c + 256] + b[c + 256]);
}

// ---------------- windowed attention (float4-vectorized LDS) -----------------
__global__ __launch_bounds__(128) void attn_kernel(
    const __half* __restrict__ qkv, const float* __restrict__ rpb,
    __half* __restrict__ out)
{
    int w    = blockIdx.x >> 4;
    int head = blockIdx.x & 15;
    // 16B-aligned, 144B row stride -> float4 LDS legal on every row
    __shared__ __align__(16) float qs[49][36], ks[49][36], vs[49][36];
    __shared__ __align__(16) float S[49][52];   // 208B rows, float4-able
    int tid = threadIdx.x;

    for (int idx = tid; idx < 49 * 16; idx += 128) {
        int n = idx >> 4, dp = (idx & 15) * 2;
        const __half* base = qkv + (size_t)(w * 49 + n) * 1536 + head * 32 + dp;
        float2 q2 = __half22float2(*(const __half2*)(base));
        float2 k2 = __half22float2(*(const __half2*)(base + 512));
        float2 v2 = __half22float2(*(const __half2*)(base + 1024));
        qs[n][dp] = q2.x; qs[n][dp + 1] = q2.y;
        ks[n][dp] = k2.x; ks[n][dp + 1] = k2.y;
        vs[n][dp] = v2.x; vs[n][dp + 1] = v2.y;
    }
    __syncthreads();

    int wh = w >> 4, ww = w & 15;
    // QK^T: q-row in registers (float4), ks via LDS.128
    for (int idx = tid; idx < 49 * 7; idx += 128) {
        int i  = idx / 7;
        int jb = (idx % 7) * 7;
        float4 qr[8];
        #pragma unroll
        for (int d4 = 0; d4 < 8; d4++) qr[d4] = *(const float4*)&qs[i][d4 * 4];
        int ri = i / 7, ci = i % 7;
        int hi = wh * 7 + ri, wi = ww * 7 + ci;
        int regi = ((hi < 105) ? 0 : (hi < 109 ? 1 : 2)) * 3 + ((wi < 105) ? 0 : (wi < 109 ? 1 : 2));
        #pragma unroll
        for (int jo = 0; jo < 7; jo++) {
            int j = jb + jo;
            float s = 0.f;
            #pragma unroll
            for (int d4 = 0; d4 < 8; d4++) {
                float4 k4 = *(const float4*)&ks[j][d4 * 4];
                s += qr[d4].x * k4.x + qr[d4].y * k4.y + qr[d4].z * k4.z + qr[d4].w * k4.w;
            }
            s *= 0.17677669529663687f;
            int rj = j / 7, cj = j % 7;
            s += rpb[((ri - rj + 6) * 13 + (ci - cj + 6)) * 16 + head];
            int hj = wh * 7 + rj, wj = ww * 7 + cj;
            int regj = ((hj < 105) ? 0 : (hj < 109 ? 1 : 2)) * 3 + ((wj < 105) ? 0 : (wj < 109 ? 1 : 2));
            if (regi != regj) s -= 1e9f;
            S[i][j] = s;
        }
    }
    __syncthreads();

    if (tid < 49) {
        float4* row = (float4*)&S[tid][0];
        float last = S[tid][48];
        float mx = last;
        #pragma unroll
        for (int q4 = 0; q4 < 12; q4++) {
            float4 v = row[q4];
            mx = fmaxf(mx, fmaxf(fmaxf(v.x, v.y), fmaxf(v.z, v.w)));
        }
        float sum = 0.f;
        #pragma unroll
        for (int q4 = 0; q4 < 12; q4++) {
            float4 v = row[q4];
            v.x = expf(v.x - mx); v.y = expf(v.y - mx);
            v.z = expf(v.z - mx); v.w = expf(v.w - mx);
            sum += v.x + v.y + v.z + v.w;
            row[q4] = v;
        }
        last = expf(last - mx); sum += last;
        float inv = 1.0f / sum;
        #pragma unroll
        for (int q4 = 0; q4 < 12; q4++) {
            float4 v = row[q4];
            v.x *= inv; v.y *= inv; v.z *= inv; v.w *= inv;
            row[q4] = v;
        }
        S[tid][48] = last * inv;
    }
    __syncthreads();

    // S @ V with float4 V loads
    for (int idx = tid; idx < 49 * 8; idx += 128) {
        int i  = idx >> 3;
        int dq = (idx & 7) * 4;
        float4 acc = make_float4(0.f, 0.f, 0.f, 0.f);
        #pragma unroll 7
        for (int j = 0; j < 49; j++) {
            float sv = S[i][j];
            float4 v = *(const float4*)&vs[j][dq];
            acc.x += sv * v.x; acc.y += sv * v.y;
            acc.z += sv * v.z; acc.w += sv * v.w;
        }
        __half* op = out + (size_t)(w * 49 + i) * 512 + head * 32 + dq;
        *(__half2*)(op)     = __floats2half2_rn(acc.x, acc.y);
        *(__half2*)(op + 2) = __floats2half2_rn(acc.z, acc.w);
    }
}

// ---------------- fp16 mma.sync GEMM with ldmatrix (unchanged from R10) ------
#define BM 128
#define BN 128
#define BKH 64
#define PADH 72
#define ROWB 144
#define BUF_HALFS (BM * PADH)
#define SM_BYTES (4 * BUF_HALFS * 2)

__device__ __forceinline__ void mma16(float* c, const uint32_t* a, uint32_t b0, uint32_t b1) {
    asm volatile(
        "mma.sync.aligned.m16n8k16.row.col.f32.f16.f16.f32 "
        "{%0,%1,%2,%3}, {%4,%5,%6,%7}, {%8,%9}, {%0,%1,%2,%3};"
        : "+f"(c[0]), "+f"(c[1]), "+f"(c[2]), "+f"(c[3])
        : "r"(a[0]), "r"(a[1]), "r"(a[2]), "r"(a[3]), "r"(b0), "r"(b1));
}

__device__ __forceinline__ void load_chunk(
    const __half* __restrict__ A, const __half* __restrict__ B, int K,
    int m0, int n0, int tid, uint32_t a_s, uint32_t b_s, int ch)
{
    int kb = ch * BKH;
    #pragma unroll
    for (int t = 0; t < 8; t++) {
        int idx = tid + t * 256;
        int li  = idx & 1023;
        int r = li >> 3, c8 = li & 7;
        uint32_t so = (uint32_t)(r * ROWB + c8 * 16);
        if (idx < 1024)
            cp16(a_s + so, A + (size_t)(m0 + r) * K + kb + c8 * 8);
        else
            cp16(b_s + so, B + (size_t)(n0 + r) * K + kb + c8 * 8);
    }
    asm volatile("cp.async.commit_group;" ::: "memory");
}

__global__ __launch_bounds__(256, 2) void gemm_mma(
    const __half* __restrict__ A, const __half* __restrict__ B,
    const float* __restrict__ bias, const float* __restrict__ res,
    void* __restrict__ Cv, int N, int K, int mode)
{
    extern __shared__ __half sm[];
    uint32_t sb = smem_u32(sm);
    int tid = threadIdx.x;
    int wid = tid >> 5, lane = tid & 31;
    int g = lane >> 2, t4 = lane & 3;
    int wm = wid >> 2, wn = wid & 3;
    int m0 = blockIdx.y * BM, n0 = blockIdx.x * BN;

    uint32_t Asu[2] = { sb,                       sb + 2 * BUF_HALFS * 2 };
    uint32_t Bsu[2] = { sb + BUF_HALFS * 2,       sb + 3 * BUF_HALFS * 2 };

    uint32_t a_off = (uint32_t)(wm * 64 + (lane & 15)) * ROWB + ((lane >> 4) ? 16u : 0u);
    uint32_t b_off = (uint32_t)(wn * 32 + lane) * ROWB;

    float c[4][4][4];
    #pragma unroll
    for (int i = 0; i < 4; i++)
        #pragma unroll
        for (int j = 0; j < 4; j++)
            #pragma unroll
            for (int r = 0; r < 4; r++) c[i][j][r] = 0.f;

    int nch = K / BKH;
    load_chunk(A, B, K, m0, n0, tid, Asu[0], Bsu[0], 0);
    load_chunk(A, B, K, m0, n0, tid, Asu[1], Bsu[1], 1);

    for (int ch = 0; ch < nch; ch++) {
        if (ch + 1 < nch) asm volatile("cp.async.wait_group 1;" ::: "memory");
        else              asm volatile("cp.async.wait_group 0;" ::: "memory");
        __syncthreads();

        uint32_t a_base = Asu[ch & 1] + a_off;
        uint32_t b_base = Bsu[ch & 1] + b_off;
        #pragma unroll
        for (int ks = 0; ks < 4; ks++) {
            uint32_t kbyte = ks * 32;
            uint32_t af[4][4], bq0[4], bq1[4];
            #pragma unroll
            for (int mt = 0; mt < 4; mt++)
                ldmx4(af[mt], a_base + mt * (16 * ROWB) + kbyte);
            ldmx4(bq0, b_base + kbyte);
            ldmx4(bq1, b_base + kbyte + 16);
            #pragma unroll
            for (int mt = 0; mt < 4; mt++)
                #pragma unroll
                for (int nt = 0; nt < 4; nt++)
                    mma16(c[mt][nt], af[mt], bq0[nt], bq1[nt]);
        }
        __syncthreads();
        if (ch + 2 < nch)
            load_chunk(A, B, K, m0, n0, tid, Asu[ch & 1], Bsu[ch & 1], ch + 2);
    }

    if (mode == 0) {
        __half* C = (__half*)Cv;
        #pragma unroll
        for (int mt = 0; mt < 4; mt++)
            #pragma unroll
            for (int hf = 0; hf < 2; hf++) {
                int m = m0 + wm * 64 + mt * 16 + g + hf * 8;
                #pragma unroll
                for (int nt = 0; nt < 4; nt++) {
                    int n = n0 + wn * 32 + nt * 8 + t4 * 2;
                    float v0 = c[mt][nt][hf * 2 + 0] + bias[n];
                    float v1 = c[mt][nt][hf * 2 + 1] + bias[n + 1];
                    *(__half2*)(C + (size_t)m * N + n) = __floats2half2_rn(v0, v1);
                }
            }
    } else if (mode == 1) {
        __half* C = (__half*)Cv;
        #pragma unroll
        for (int mt = 0; mt < 4; mt++)
            #pragma unroll
            for (int hf = 0; hf < 2; hf++) {
                int m = m0 + wm * 64 + mt * 16 + g + hf * 8;
                #pragma unroll
                for (int nt = 0; nt < 4; nt++) {
                    int n = n0 + wn * 32 + nt * 8 + t4 * 2;
                    float v0 = gelu_tanh(c[mt][nt][hf * 2 + 0] + bias[n]);
                    float v1 = gelu_tanh(c[mt][nt][hf * 2 + 1] + bias[n + 1]);
                    *(__half2*)(C + (size_t)m * N + n) = __floats2half2_rn(v0, v1);
                }
            }
    } else if (mode == 2) {
        float* C = (float*)Cv;
        #pragma unroll
        for (int mt = 0; mt < 4; mt++)
            #pragma unroll
            for (int hf = 0; hf < 2; hf++) {
                int m = m0 + wm * 64 + mt * 16 + g + hf * 8;
                int p = tok2pix(m);
                #pragma unroll
                for (int nt = 0; nt < 4; nt++) {
                    int n = n0 + wn * 32 + nt * 8 + t4 * 2;
                    float2 v = make_float2(
                        c[mt][nt][hf * 2 + 0] + bias[n]     + res[(size_t)n * HW + p],
                        c[mt][nt][hf * 2 + 1] + bias[n + 1] + res[(size_t)(n + 1) * HW + p]);
                    *(float2*)(C + (size_t)p * 512 + n) = v;
                }
            }
    } else {  // mode 3
        float* C = (float*)Cv;
        #pragma unroll
        for (int mt = 0; mt < 4; mt++)
            #pragma unroll
            for (int hf = 0; hf < 2; hf++) {
                int m = m0 + wm * 64 + mt * 16 + g + hf * 8;
                #pragma unroll
                for (int nt = 0; nt < 4; nt++) {
                    int n = n0 + wn * 32 + nt * 8 + t4 * 2;
                    float r0 = res[(size_t)m * 512 + n];
                    float r1 = res[(size_t)m * 512 + n + 1];
                    C[(size_t)n * HW + m]       = c[mt][nt][hf * 2 + 0] + bias[n]     + r0;
                    C[(size_t)(n + 1) * HW + m] = c[mt][nt][hf * 2 + 1] + bias[n + 1] + r1;
                }
            }
    }
}

// ---------------- launcher --------------------------------------------------
extern "C" void kernel_launch(void* const* d_in, const int* in_sizes, int n_in,
                              void* d_out, int out_size)
{
    const float* x     = (const float*)d_in[0];
    const float* n1w   = (const float*)d_in[1];
    const float* n1b   = (const float*)d_in[2];
    const float* qkvw  = (const float*)d_in[3];
    const float* qkvb  = (const float*)d_in[4];
    const float* projw = (const float*)d_in[5];
    const float* projb = (const float*)d_in[6];
    const float* rpb   = (const float*)d_in[7];
    const float* n2w   = (const float*)d_in[8];
    const float* n2b   = (const float*)d_in[9];
    const float* f1w   = (const float*)d_in[10];
    const float* f1b   = (const float*)d_in[11];
    const float* f2w   = (const float*)d_in[12];
    const float* f2b   = (const float*)d_in[13];
    float* out = (float*)d_out;

    __half *xw, *qkv, *att, *x2, *h, *wq, *wp, *w1, *w2;
    float *x1;
    cudaGetSymbolAddress((void**)&xw,  g_xw);
    cudaGetSymbolAddress((void**)&qkv, g_qkv);
    cudaGetSymbolAddress((void**)&att, g_att);
    cudaGetSymbolAddress((void**)&x1,  g_x1);
    cudaGetSymbolAddress((void**)&x2,  g_x2);
    cudaGetSymbolAddress((void**)&h,   g_h);
    cudaGetSymbolAddress((void**)&wq,  g_wq);
    cudaGetSymbolAddress((void**)&wp,  g_wp);
    cudaGetSymbolAddress((void**)&w1,  g_w1);
    cudaGetSymbolAddress((void**)&w2,  g_w2);

    cudaFuncSetAttribute(gemm_mma, cudaFuncAttributeMaxDynamicSharedMemorySize, SM_BYTES);

    // 0) all weights fp32 -> fp16 in one launch
    f2h_all<<<512, 256>>>(qkvw, projw, f1w, f2w, wq, wp, w1, w2);

    // 1) LN1 + shift + window partition (fp16 out, coalesced)
    ln1_kernel<<<HW / 32, 256>>>(x, n1w, n1b, xw);
    // 2) QKV GEMM [12544,512] x [1536,512]^T -> fp16
    gemm_mma<<<dim3(1536 / 128, NTOK / 128), 256, SM_BYTES>>>(xw, wq, qkvb, nullptr, qkv, 1536, 512, 0);
    // 3) windowed attention -> fp16
    attn_kernel<<<256 * 16, 128>>>(qkv, rpb, att);
    // 4) proj GEMM + unshift/unpartition + residual(x) -> x1 [p,C] fp32
    gemm_mma<<<dim3(512 / 128, NTOK / 128), 256, SM_BYTES>>>(att, wp, projb, x, x1, 512, 512, 2);
    // 5) LN2 (fp16 out)
    ln2_kernel<<<HW, 256>>>(x1, n2w, n2b, x2);
    // 6) FC1 + GELU (fp16 out)
    gemm_mma<<<dim3(2048 / 128, NTOK / 128), 256, SM_BYTES>>>(x2, w1, f1b, nullptr, h, 2048, 512, 1);
    // 7) FC2 + residual(x1) + transpose to [C,H,W] output
    gemm_mma<<<dim3(512 / 128, NTOK / 128), 256, SM_BYTES>>>(h, w2, f2b, x1, out, 512, 2048, 3);
}